// round 1
// baseline (speedup 1.0000x reference)
#include <cuda_runtime.h>
#include <cuda_bf16.h>
#include <math.h>

// Problem constants (fixed by the reference)
#define NN 50000
#define EE 200000
#define DD 384
#define HH 2
#define DHH 192

// ---------------- device scratch (allocation-free requirement) ----------------
__device__ float g_q[(size_t)NN * DD];
__device__ float g_k[(size_t)NN * DD];
__device__ float g_v[(size_t)NN * DD];
__device__ float g_agg[(size_t)NN * DD];
__device__ float g_tmp[(size_t)NN * DD];
__device__ float g_score[(size_t)EE * HH];
__device__ float g_smax[(size_t)NN * HH];
__device__ float g_denom[(size_t)NN * HH];

// ---------------- helpers ----------------
__device__ __forceinline__ void atomicMaxF(float* addr, float val) {
    int old = __float_as_int(*addr);
    while (__int_as_float(old) < val) {
        int prev = atomicCAS((int*)addr, old, __float_as_int(val));
        if (prev == old) break;
        old = prev;
    }
}

// ---------------- init: zero agg, init smax/denom ----------------
__global__ __launch_bounds__(256) void init_kernel() {
    int idx = blockIdx.x * 256 + threadIdx.x;
    if (idx < NN * DD) g_agg[idx] = 0.0f;
    if (idx < NN * HH) { g_smax[idx] = -3.0e38f; g_denom[idx] = 0.0f; }
}

// ---------------- SGEMM: C[M,384] = A[M,384] @ B[384,384] (+resid) ----------------
// 128x128 tile, BK=8, 256 threads, 8x8 per-thread microtile.
__global__ __launch_bounds__(256) void sgemm384(
    const float* __restrict__ A, const float* __restrict__ B,
    float* __restrict__ C, int M, const float* __restrict__ resid)
{
    __shared__ float As[8][136];   // padded to avoid bank conflicts, keeps 16B align
    __shared__ float Bs[8][128];

    const int tid = threadIdx.x;
    const int tx = tid & 15;       // col group 0..15
    const int ty = tid >> 4;       // row group 0..15
    const int rowBase = blockIdx.y * 128;
    const int colBase = blockIdx.x * 128;

    float acc[8][8];
#pragma unroll
    for (int i = 0; i < 8; i++)
#pragma unroll
        for (int j = 0; j < 8; j++) acc[i][j] = 0.0f;

    const int aRow  = tid >> 1;          // 0..127
    const int aCol4 = (tid & 1) * 4;     // 0 or 4
    const int bRow  = tid >> 5;          // 0..7
    const int bCol4 = (tid & 31) * 4;    // 0..124

    for (int k0 = 0; k0 < 384; k0 += 8) {
        float4 av = make_float4(0.f, 0.f, 0.f, 0.f);
        int gRow = rowBase + aRow;
        if (gRow < M)
            av = *reinterpret_cast<const float4*>(A + (size_t)gRow * DD + k0 + aCol4);
        As[aCol4 + 0][aRow] = av.x;
        As[aCol4 + 1][aRow] = av.y;
        As[aCol4 + 2][aRow] = av.z;
        As[aCol4 + 3][aRow] = av.w;

        float4 bv = *reinterpret_cast<const float4*>(
            B + (size_t)(k0 + bRow) * DD + colBase + bCol4);
        *reinterpret_cast<float4*>(&Bs[bRow][bCol4]) = bv;

        __syncthreads();

#pragma unroll
        for (int k = 0; k < 8; ++k) {
            float a[8], b[8];
            *(float4*)&a[0] = *(const float4*)&As[k][ty * 8];
            *(float4*)&a[4] = *(const float4*)&As[k][ty * 8 + 4];
            *(float4*)&b[0] = *(const float4*)&Bs[k][tx * 8];
            *(float4*)&b[4] = *(const float4*)&Bs[k][tx * 8 + 4];
#pragma unroll
            for (int i = 0; i < 8; i++)
#pragma unroll
                for (int j = 0; j < 8; j++)
                    acc[i][j] += a[i] * b[j];
        }
        __syncthreads();
    }

#pragma unroll
    for (int i = 0; i < 8; i++) {
        int r = rowBase + ty * 8 + i;
        if (r >= M) continue;
#pragma unroll
        for (int j = 0; j < 8; j += 4) {
            int c = colBase + tx * 8 + j;
            size_t off = (size_t)r * DD + c;
            float4 val = make_float4(acc[i][j], acc[i][j + 1], acc[i][j + 2], acc[i][j + 3]);
            if (resid) {
                float4 rv = *reinterpret_cast<const float4*>(resid + off);
                val.x += rv.x; val.y += rv.y; val.z += rv.z; val.w += rv.w;
            }
            *reinterpret_cast<float4*>(C + off) = val;
        }
    }
}

// ---------------- edge scores: warp per edge ----------------
__global__ __launch_bounds__(256) void edge_score(
    const int* __restrict__ src, const int* __restrict__ dst,
    const float* __restrict__ eattr, const float* __restrict__ WE)
{
    const int e = blockIdx.x * 8 + (threadIdx.x >> 5);
    if (e >= EE) return;
    const int lane = threadIdx.x & 31;
    const int s = src[e], t = dst[e];
    const float ea = eattr[e];
    const float* qrow = g_q + (size_t)t * DD;
    const float* krow = g_k + (size_t)s * DD;

    float acc0 = 0.f, acc1 = 0.f;
#pragma unroll
    for (int j = 0; j < 6; j++) {
        int d0 = lane + 32 * j;      // head 0: 0..191
        int d1 = d0 + DHH;           // head 1
        acc0 += qrow[d0] * (krow[d0] + ea * WE[d0]);
        acc1 += qrow[d1] * (krow[d1] + ea * WE[d1]);
    }
#pragma unroll
    for (int o = 16; o > 0; o >>= 1) {
        acc0 += __shfl_down_sync(0xffffffffu, acc0, o);
        acc1 += __shfl_down_sync(0xffffffffu, acc1, o);
    }
    if (lane == 0) {
        const float SCL = 0.07216878364870323f;  // 1/sqrt(192)
        float s0 = acc0 * SCL, s1 = acc1 * SCL;
        g_score[(size_t)e * 2 + 0] = s0;
        g_score[(size_t)e * 2 + 1] = s1;
        atomicMaxF(&g_smax[(size_t)t * 2 + 0], s0);
        atomicMaxF(&g_smax[(size_t)t * 2 + 1], s1);
    }
}

// ---------------- edge aggregate (unnormalized): warp per edge ----------------
__global__ __launch_bounds__(256) void edge_agg(
    const int* __restrict__ src, const int* __restrict__ dst,
    const float* __restrict__ eattr, const float* __restrict__ WE)
{
    const int e = blockIdx.x * 8 + (threadIdx.x >> 5);
    if (e >= EE) return;
    const int lane = threadIdx.x & 31;
    const int s = src[e], t = dst[e];
    const float ea = eattr[e];

    float ex0 = expf(g_score[(size_t)e * 2 + 0] - g_smax[(size_t)t * 2 + 0]);
    float ex1 = expf(g_score[(size_t)e * 2 + 1] - g_smax[(size_t)t * 2 + 1]);
    if (lane == 0) atomicAdd(&g_denom[(size_t)t * 2 + 0], ex0);
    if (lane == 1) atomicAdd(&g_denom[(size_t)t * 2 + 1], ex1);

    const float* vrow = g_v + (size_t)s * DD;
    float* arow = g_agg + (size_t)t * DD;
#pragma unroll
    for (int j = 0; j < 6; j++) {
        int d0 = lane + 32 * j;
        int d1 = d0 + DHH;
        atomicAdd(&arow[d0], ex0 * (vrow[d0] + ea * WE[d0]));
        atomicAdd(&arow[d1], ex1 * (vrow[d1] + ea * WE[d1]));
    }
}

// ---------------- normalize agg by softmax denominator ----------------
__global__ __launch_bounds__(256) void normalize_agg() {
    int idx = blockIdx.x * 256 + threadIdx.x;
    if (idx >= NN * DD) return;
    int n = idx / DD;
    int d = idx - n * DD;
    int h = (d >= DHH) ? 1 : 0;
    g_agg[idx] = g_agg[idx] / (g_denom[(size_t)n * 2 + h] + 1e-16f);
}

// ---------------- layernorm over g_tmp (residual already added) ----------------
__global__ __launch_bounds__(128) void ln_kernel(
    const float* __restrict__ gw, const float* __restrict__ bw,
    float* __restrict__ out)
{
    const int n = blockIdx.x;
    const int tid = threadIdx.x;
    const float* x = g_tmp + (size_t)n * DD;
    float v0 = x[tid], v1 = x[tid + 128], v2 = x[tid + 256];
    float s = v0 + v1 + v2;
    float sq = v0 * v0 + v1 * v1 + v2 * v2;
#pragma unroll
    for (int o = 16; o > 0; o >>= 1) {
        s  += __shfl_down_sync(0xffffffffu, s, o);
        sq += __shfl_down_sync(0xffffffffu, sq, o);
    }
    __shared__ float ss[4], ssq[4];
    int w = tid >> 5, l = tid & 31;
    if (l == 0) { ss[w] = s; ssq[w] = sq; }
    __syncthreads();
    if (tid == 0) {
        float S = ss[0] + ss[1] + ss[2] + ss[3];
        float SQ = ssq[0] + ssq[1] + ssq[2] + ssq[3];
        float mu = S * (1.0f / DD);
        float var = SQ * (1.0f / DD) - mu * mu;
        ss[0] = mu;
        ssq[0] = rsqrtf(var + 1e-5f);
    }
    __syncthreads();
    float mu = ss[0], inv = ssq[0];
    size_t base = (size_t)n * DD;
    out[base + tid]       = (v0 - mu) * inv * gw[tid]       + bw[tid];
    out[base + tid + 128] = (v1 - mu) * inv * gw[tid + 128] + bw[tid + 128];
    out[base + tid + 256] = (v2 - mu) * inv * gw[tid + 256] + bw[tid + 256];
}

// ---------------- launch ----------------
extern "C" void kernel_launch(void* const* d_in, const int* in_sizes, int n_in,
                              void* d_out, int out_size)
{
    const float* emb   = (const float*)d_in[0];
    const int*   eidx  = (const int*)  d_in[1];   // [2, E]
    const float* eattr = (const float*)d_in[2];   // [E, 1]
    const float* WQ    = (const float*)d_in[3];
    const float* WK    = (const float*)d_in[4];
    const float* WV    = (const float*)d_in[5];
    const float* WE    = (const float*)d_in[6];   // [1, 384]
    const float* WO    = (const float*)d_in[7];
    const float* ln_g  = (const float*)d_in[8];
    const float* ln_b  = (const float*)d_in[9];
    float* out = (float*)d_out;

    const int* src = eidx;
    const int* dst = eidx + EE;

    // init scratch (agg=0, smax=-inf, denom=0)
    init_kernel<<<(NN * DD + 255) / 256, 256>>>();

    // Q/K/V projections
    dim3 ggrid(DD / 128, (NN + 127) / 128);
    float *dq, *dk, *dv, *dagg, *dtmp;
    cudaGetSymbolAddress((void**)&dq,   g_q);
    cudaGetSymbolAddress((void**)&dk,   g_k);
    cudaGetSymbolAddress((void**)&dv,   g_v);
    cudaGetSymbolAddress((void**)&dagg, g_agg);
    cudaGetSymbolAddress((void**)&dtmp, g_tmp);

    sgemm384<<<ggrid, 256>>>(emb, WQ, dq, NN, nullptr);
    sgemm384<<<ggrid, 256>>>(emb, WK, dk, NN, nullptr);
    sgemm384<<<ggrid, 256>>>(emb, WV, dv, NN, nullptr);

    // edge scores + segment max
    edge_score<<<(EE + 7) / 8, 256>>>(src, dst, eattr, WE);

    // exp, denom, unnormalized aggregation
    edge_agg<<<(EE + 7) / 8, 256>>>(src, dst, eattr, WE);

    // divide by denom
    normalize_agg<<<(NN * DD + 255) / 256, 256>>>();

    // output projection + residual into g_tmp
    sgemm384<<<ggrid, 256>>>(dagg, WO, dtmp, NN, emb);

    // layernorm -> out
    ln_kernel<<<NN, 128>>>(ln_g, ln_b, out);
}

// round 3
// speedup vs baseline: 1.9259x; 1.9259x over previous
#include <cuda_runtime.h>
#include <cuda_bf16.h>
#include <math.h>
#include <stdint.h>

// Problem constants (fixed by the reference)
#define NN 50000
#define EE 200000
#define DD 384
#define HH 2
#define DHH 192

// ---------------- device scratch (allocation-free requirement) ----------------
__device__ float g_q[(size_t)NN * DD];
__device__ float g_k[(size_t)NN * DD];
__device__ float g_v[(size_t)NN * DD];
__device__ float g_agg[(size_t)NN * DD];
__device__ float g_tmp[(size_t)NN * DD];
__device__ float g_score[(size_t)EE * HH];
__device__ float g_smax[(size_t)NN * HH];
__device__ float g_denom[(size_t)NN * HH];

__device__ __nv_bfloat16 g_emb_hi[(size_t)NN * DD];
__device__ __nv_bfloat16 g_emb_lo[(size_t)NN * DD];
__device__ __nv_bfloat16 g_agg_hi[(size_t)NN * DD];
__device__ __nv_bfloat16 g_agg_lo[(size_t)NN * DD];
__device__ __nv_bfloat16 g_wt_hi[(size_t)3 * DD * DD];   // [WQ|WK|WV]^T  [1152(N), 384(K)]
__device__ __nv_bfloat16 g_wt_lo[(size_t)3 * DD * DD];
__device__ __nv_bfloat16 g_wo_hi[(size_t)DD * DD];       // WO^T [384, 384]
__device__ __nv_bfloat16 g_wo_lo[(size_t)DD * DD];

// ---------------- PTX helpers (baseline sm_90/sm_103 features only) ----------------
__device__ __forceinline__ uint32_t smem_to_u32(const void* p) {
    uint32_t a;
    asm("{ .reg .u64 t; cvta.to.shared.u64 t, %1; cvt.u32.u64 %0, t; }" : "=r"(a) : "l"(p));
    return a;
}
__device__ __forceinline__ void ldsm_x4(uint32_t* r, uint32_t addr) {
    asm volatile("ldmatrix.sync.aligned.m8n8.x4.shared.b16 {%0,%1,%2,%3}, [%4];"
        : "=r"(r[0]), "=r"(r[1]), "=r"(r[2]), "=r"(r[3]) : "r"(addr));
}
__device__ __forceinline__ void mma_bf16(float* c, const uint32_t* a, const uint32_t* b) {
    asm volatile(
        "mma.sync.aligned.m16n8k16.row.col.f32.bf16.bf16.f32 "
        "{%0,%1,%2,%3}, {%4,%5,%6,%7}, {%8,%9}, {%0,%1,%2,%3};"
        : "+f"(c[0]), "+f"(c[1]), "+f"(c[2]), "+f"(c[3])
        : "r"(a[0]), "r"(a[1]), "r"(a[2]), "r"(a[3]), "r"(b[0]), "r"(b[1]));
}
__device__ __forceinline__ void cp16(uint32_t dst, const void* src, bool valid) {
    int sz = valid ? 16 : 0;
    asm volatile("cp.async.cg.shared.global [%0], [%1], 16, %2;"
        :: "r"(dst), "l"(src), "r"(sz) : "memory");
}

// smem geometry: 4 operand arrays (Ahi,Alo,Bhi,Blo), 128 rows x 80B pitch, double-buffered
#define PITCH 80
#define ARR   10240          // 128 * 80
#define STG   40960          // 4 * ARR
#define SM_TOTAL (2 * STG)   // 81920

// ---------------- bf16x3 HMMA GEMM ----------------
// C[m, colBase+n] = sum_k A[m,k] * Bt[bx*128+n, k]  (+resid)
__global__ __launch_bounds__(256)
void gemm_tc(const __nv_bfloat16* __restrict__ Ahi, const __nv_bfloat16* __restrict__ Alo,
             const __nv_bfloat16* __restrict__ Bhi, const __nv_bfloat16* __restrict__ Blo,
             float* __restrict__ C0, float* __restrict__ C1, float* __restrict__ C2,
             int M, const float* __restrict__ resid)
{
    extern __shared__ char smem[];
    const uint32_t sb = smem_to_u32(smem);
    const int tid = threadIdx.x;
    const int wid = tid >> 5;
    const int lane = tid & 31;
    const int warp_m = wid & 1;     // 0..1
    const int warp_n = wid >> 1;    // 0..3
    const int rowBase = blockIdx.y * 128;
    const int mat = blockIdx.x / 3;
    const int colBase = (blockIdx.x % 3) * 128;
    const int btRowBase = blockIdx.x * 128;
    float* C = (mat == 0) ? C0 : (mat == 1 ? C1 : C2);

    float acc[4][4][4];
#pragma unroll
    for (int i = 0; i < 4; i++)
#pragma unroll
        for (int j = 0; j < 4; j++)
#pragma unroll
            for (int l = 0; l < 4; l++) acc[i][j][l] = 0.0f;

    const __nv_bfloat16* srcA[2] = { Ahi, Alo };
    const __nv_bfloat16* srcB[2] = { Bhi, Blo };

    // ---- async stage loader ----
    auto load_stage = [&](int buf, int s) {
        const int k0 = s * 32;
#pragma unroll
        for (int i = 0; i < 8; i++) {
            int id = i * 256 + tid;          // 0..2047
            int arr = id >> 9;               // 0..3
            int cid = id & 511;
            int row = cid >> 2;              // 0..127
            int c = cid & 3;                 // 16B chunk
            uint32_t dst = sb + buf * STG + arr * ARR + row * PITCH + c * 16;
            const __nv_bfloat16* src;
            bool valid = true;
            if (arr < 2) {
                int gRow = rowBase + row;
                valid = (gRow < M);
                int gr = valid ? gRow : 0;
                src = srcA[arr] + (size_t)gr * DD + k0 + c * 8;
            } else {
                src = srcB[arr - 2] + (size_t)(btRowBase + row) * DD + k0 + c * 8;
            }
            cp16(dst, src, valid);
        }
        asm volatile("cp.async.commit_group;" ::: "memory");
    };

    load_stage(0, 0);

    for (int s = 0; s < 12; s++) {
        if (s + 1 < 12) {
            load_stage((s + 1) & 1, s + 1);
            asm volatile("cp.async.wait_group 1;" ::: "memory");
        } else {
            asm volatile("cp.async.wait_group 0;" ::: "memory");
        }
        __syncthreads();

        const uint32_t st = sb + (s & 1) * STG;
#pragma unroll
        for (int kk = 0; kk < 2; kk++) {
            uint32_t ah[4][4], al[4][4], bh[2][4], bl[2][4];
            const int arow = warp_m * 64;
#pragma unroll
            for (int mt = 0; mt < 4; mt++) {
                uint32_t addr = st + (uint32_t)((arow + mt * 16 + (lane & 15)) * PITCH
                              + kk * 32 + ((lane >> 4) & 1) * 16);
                ldsm_x4(ah[mt], addr);
                ldsm_x4(al[mt], addr + ARR);
            }
#pragma unroll
            for (int p = 0; p < 2; p++) {
                int grp = lane >> 3;                              // 0..3
                int row = warp_n * 32 + (p * 2 + (grp >> 1)) * 8 + (lane & 7);
                uint32_t addr = st + 2 * ARR + (uint32_t)(row * PITCH
                              + kk * 32 + (grp & 1) * 16);
                ldsm_x4(bh[p], addr);
                ldsm_x4(bl[p], addr + ARR);
            }
#pragma unroll
            for (int mt = 0; mt < 4; mt++) {
#pragma unroll
                for (int nt = 0; nt < 4; nt++) {
                    const uint32_t* B2h = &bh[nt >> 1][(nt & 1) * 2];
                    const uint32_t* B2l = &bl[nt >> 1][(nt & 1) * 2];
                    mma_bf16(acc[mt][nt], ah[mt], B2h);
                    mma_bf16(acc[mt][nt], ah[mt], B2l);
                    mma_bf16(acc[mt][nt], al[mt], B2h);
                }
            }
        }
        __syncthreads();
    }

    // ---- epilogue: direct register -> gmem float2 stores (+resid) ----
#pragma unroll
    for (int mt = 0; mt < 4; mt++) {
        int r0 = rowBase + warp_m * 64 + mt * 16 + (lane >> 2);
#pragma unroll
        for (int nt = 0; nt < 4; nt++) {
            int col = colBase + warp_n * 32 + nt * 8 + (lane & 3) * 2;
#pragma unroll
            for (int half = 0; half < 2; half++) {
                int r = r0 + half * 8;
                if (r >= M) continue;
                size_t off = (size_t)r * DD + col;
                float2 v = make_float2(acc[mt][nt][half * 2], acc[mt][nt][half * 2 + 1]);
                if (resid) {
                    float2 rv = *reinterpret_cast<const float2*>(resid + off);
                    v.x += rv.x; v.y += rv.y;
                }
                *reinterpret_cast<float2*>(C + off) = v;
            }
        }
    }
}

// ---------------- conversions ----------------
__global__ __launch_bounds__(256) void conv_emb(const float* __restrict__ emb) {
    int idx = blockIdx.x * 256 + threadIdx.x;
    if (idx >= NN * DD) return;
    float x = emb[idx];
    __nv_bfloat16 hi = __float2bfloat16(x);
    __nv_bfloat16 lo = __float2bfloat16(x - __bfloat162float(hi));
    g_emb_hi[idx] = hi;
    g_emb_lo[idx] = lo;
}

__global__ __launch_bounds__(256) void conv_weights(
    const float* __restrict__ WQ, const float* __restrict__ WK,
    const float* __restrict__ WV, const float* __restrict__ WO)
{
    int idx = blockIdx.x * 256 + threadIdx.x;
    if (idx >= 4 * DD * DD) return;
    int mat = idx / (DD * DD);
    int rem = idx - mat * (DD * DD);
    int n = rem / DD;
    int k = rem - n * DD;
    const float* W = (mat == 0) ? WQ : (mat == 1 ? WK : (mat == 2 ? WV : WO));
    float x = W[(size_t)k * DD + n];
    __nv_bfloat16 hi = __float2bfloat16(x);
    __nv_bfloat16 lo = __float2bfloat16(x - __bfloat162float(hi));
    if (mat < 3) {
        size_t o = (size_t)mat * DD * DD + (size_t)n * DD + k;
        g_wt_hi[o] = hi; g_wt_lo[o] = lo;
    } else {
        size_t o = (size_t)n * DD + k;
        g_wo_hi[o] = hi; g_wo_lo[o] = lo;
    }
}

// ---------------- init ----------------
__global__ __launch_bounds__(256) void init_kernel() {
    int idx = blockIdx.x * 256 + threadIdx.x;
    if (idx < NN * DD) g_agg[idx] = 0.0f;
    if (idx < NN * HH) { g_smax[idx] = -3.0e38f; g_denom[idx] = 0.0f; }
}

__device__ __forceinline__ void atomicMaxF(float* addr, float val) {
    int old = __float_as_int(*addr);
    while (__int_as_float(old) < val) {
        int prev = atomicCAS((int*)addr, old, __float_as_int(val));
        if (prev == old) break;
        old = prev;
    }
}

// ---------------- edge scores: warp per edge ----------------
__global__ __launch_bounds__(256) void edge_score(
    const int* __restrict__ src, const int* __restrict__ dst,
    const float* __restrict__ eattr, const float* __restrict__ WE)
{
    const int e = blockIdx.x * 8 + (threadIdx.x >> 5);
    if (e >= EE) return;
    const int lane = threadIdx.x & 31;
    const int s = src[e], t = dst[e];
    const float ea = eattr[e];
    const float* qrow = g_q + (size_t)t * DD;
    const float* krow = g_k + (size_t)s * DD;

    float acc0 = 0.f, acc1 = 0.f;
#pragma unroll
    for (int j = 0; j < 6; j++) {
        int d0 = lane + 32 * j;
        int d1 = d0 + DHH;
        acc0 += qrow[d0] * (krow[d0] + ea * WE[d0]);
        acc1 += qrow[d1] * (krow[d1] + ea * WE[d1]);
    }
#pragma unroll
    for (int o = 16; o > 0; o >>= 1) {
        acc0 += __shfl_down_sync(0xffffffffu, acc0, o);
        acc1 += __shfl_down_sync(0xffffffffu, acc1, o);
    }
    if (lane == 0) {
        const float SCL = 0.07216878364870323f;  // 1/sqrt(192)
        float s0 = acc0 * SCL, s1 = acc1 * SCL;
        g_score[(size_t)e * 2 + 0] = s0;
        g_score[(size_t)e * 2 + 1] = s1;
        atomicMaxF(&g_smax[(size_t)t * 2 + 0], s0);
        atomicMaxF(&g_smax[(size_t)t * 2 + 1], s1);
    }
}

// ---------------- edge aggregate (unnormalized): warp per edge ----------------
__global__ __launch_bounds__(256) void edge_agg(
    const int* __restrict__ src, const int* __restrict__ dst,
    const float* __restrict__ eattr, const float* __restrict__ WE)
{
    const int e = blockIdx.x * 8 + (threadIdx.x >> 5);
    if (e >= EE) return;
    const int lane = threadIdx.x & 31;
    const int s = src[e], t = dst[e];
    const float ea = eattr[e];

    float ex0 = expf(g_score[(size_t)e * 2 + 0] - g_smax[(size_t)t * 2 + 0]);
    float ex1 = expf(g_score[(size_t)e * 2 + 1] - g_smax[(size_t)t * 2 + 1]);
    if (lane == 0) atomicAdd(&g_denom[(size_t)t * 2 + 0], ex0);
    if (lane == 1) atomicAdd(&g_denom[(size_t)t * 2 + 1], ex1);

    const float* vrow = g_v + (size_t)s * DD;
    float* arow = g_agg + (size_t)t * DD;
#pragma unroll
    for (int j = 0; j < 6; j++) {
        int d0 = lane + 32 * j;
        int d1 = d0 + DHH;
        atomicAdd(&arow[d0], ex0 * (vrow[d0] + ea * WE[d0]));
        atomicAdd(&arow[d1], ex1 * (vrow[d1] + ea * WE[d1]));
    }
}

// ---------------- normalize agg by denom + split to bf16 hi/lo ----------------
__global__ __launch_bounds__(256) void normalize_agg() {
    int idx = blockIdx.x * 256 + threadIdx.x;
    if (idx >= NN * DD) return;
    int n = idx / DD;
    int d = idx - n * DD;
    int h = (d >= DHH) ? 1 : 0;
    float x = g_agg[idx] / (g_denom[(size_t)n * 2 + h] + 1e-16f);
    __nv_bfloat16 hi = __float2bfloat16(x);
    __nv_bfloat16 lo = __float2bfloat16(x - __bfloat162float(hi));
    g_agg_hi[idx] = hi;
    g_agg_lo[idx] = lo;
}

// ---------------- layernorm ----------------
__global__ __launch_bounds__(128) void ln_kernel(
    const float* __restrict__ gw, const float* __restrict__ bw,
    float* __restrict__ out)
{
    const int n = blockIdx.x;
    const int tid = threadIdx.x;
    const float* x = g_tmp + (size_t)n * DD;
    float v0 = x[tid], v1 = x[tid + 128], v2 = x[tid + 256];
    float s = v0 + v1 + v2;
    float sq = v0 * v0 + v1 * v1 + v2 * v2;
#pragma unroll
    for (int o = 16; o > 0; o >>= 1) {
        s  += __shfl_down_sync(0xffffffffu, s, o);
        sq += __shfl_down_sync(0xffffffffu, sq, o);
    }
    __shared__ float ss[4], ssq[4];
    int w = tid >> 5, l = tid & 31;
    if (l == 0) { ss[w] = s; ssq[w] = sq; }
    __syncthreads();
    if (tid == 0) {
        float S = ss[0] + ss[1] + ss[2] + ss[3];
        float SQ = ssq[0] + ssq[1] + ssq[2] + ssq[3];
        float mu = S * (1.0f / DD);
        float var = SQ * (1.0f / DD) - mu * mu;
        ss[0] = mu;
        ssq[0] = rsqrtf(var + 1e-5f);
    }
    __syncthreads();
    float mu = ss[0], inv = ssq[0];
    size_t base = (size_t)n * DD;
    out[base + tid]       = (v0 - mu) * inv * gw[tid]       + bw[tid];
    out[base + tid + 128] = (v1 - mu) * inv * gw[tid + 128] + bw[tid + 128];
    out[base + tid + 256] = (v2 - mu) * inv * gw[tid + 256] + bw[tid + 256];
}

// ---------------- launch ----------------
extern "C" void kernel_launch(void* const* d_in, const int* in_sizes, int n_in,
                              void* d_out, int out_size)
{
    const float* emb   = (const float*)d_in[0];
    const int*   eidx  = (const int*)  d_in[1];
    const float* eattr = (const float*)d_in[2];
    const float* WQ    = (const float*)d_in[3];
    const float* WK    = (const float*)d_in[4];
    const float* WV    = (const float*)d_in[5];
    const float* WE    = (const float*)d_in[6];
    const float* WO    = (const float*)d_in[7];
    const float* ln_g  = (const float*)d_in[8];
    const float* ln_b  = (const float*)d_in[9];
    float* out = (float*)d_out;

    const int* src = eidx;
    const int* dst = eidx + EE;

    cudaFuncSetAttribute(gemm_tc, cudaFuncAttributeMaxDynamicSharedMemorySize, SM_TOTAL);

    float *dq, *dk, *dv, *dtmp;
    __nv_bfloat16 *dembh, *dembl, *daggh, *daggl, *dwth, *dwtl, *dwoh, *dwol;
    cudaGetSymbolAddress((void**)&dq,    g_q);
    cudaGetSymbolAddress((void**)&dk,    g_k);
    cudaGetSymbolAddress((void**)&dv,    g_v);
    cudaGetSymbolAddress((void**)&dtmp,  g_tmp);
    cudaGetSymbolAddress((void**)&dembh, g_emb_hi);
    cudaGetSymbolAddress((void**)&dembl, g_emb_lo);
    cudaGetSymbolAddress((void**)&daggh, g_agg_hi);
    cudaGetSymbolAddress((void**)&daggl, g_agg_lo);
    cudaGetSymbolAddress((void**)&dwth,  g_wt_hi);
    cudaGetSymbolAddress((void**)&dwtl,  g_wt_lo);
    cudaGetSymbolAddress((void**)&dwoh,  g_wo_hi);
    cudaGetSymbolAddress((void**)&dwol,  g_wo_lo);

    init_kernel<<<(NN * DD + 255) / 256, 256>>>();
    conv_emb<<<(NN * DD + 255) / 256, 256>>>(emb);
    conv_weights<<<(4 * DD * DD + 255) / 256, 256>>>(WQ, WK, WV, WO);

    const int MT = (NN + 127) / 128;
    // fused Q/K/V projections
    gemm_tc<<<dim3(9, MT), 256, SM_TOTAL>>>(dembh, dembl, dwth, dwtl,
                                            dq, dk, dv, NN, nullptr);

    edge_score<<<(EE + 7) / 8, 256>>>(src, dst, eattr, WE);
    edge_agg<<<(EE + 7) / 8, 256>>>(src, dst, eattr, WE);
    normalize_agg<<<(NN * DD + 255) / 256, 256>>>();

    // output projection + residual
    gemm_tc<<<dim3(3, MT), 256, SM_TOTAL>>>(daggh, daggl, dwoh, dwol,
                                            dtmp, dtmp, dtmp, NN, emb);

    ln_kernel<<<NN, 128>>>(ln_g, ln_b, out);
}

// round 4
// speedup vs baseline: 2.2401x; 1.1632x over previous
#include <cuda_runtime.h>
#include <cuda_bf16.h>
#include <math.h>
#include <stdint.h>

// Problem constants (fixed by the reference)
#define NN 50000
#define EE 200000
#define DD 384
#define HH 2
#define DHH 192

// ---------------- device scratch (allocation-free requirement) ----------------
__device__ float g_q[(size_t)NN * DD];
__device__ float g_k[(size_t)NN * DD];
__device__ float g_v[(size_t)NN * DD];
__device__ float g_tmp[(size_t)NN * DD];

__device__ int   g_deg[NN];
__device__ int   g_rowptr[NN + 1];
__device__ int   g_cursor[NN];
__device__ int   g_esrc[EE];
__device__ float g_eea[EE];

__device__ __nv_bfloat16 g_emb_hi[(size_t)NN * DD];
__device__ __nv_bfloat16 g_emb_lo[(size_t)NN * DD];
__device__ __nv_bfloat16 g_agg_hi[(size_t)NN * DD];
__device__ __nv_bfloat16 g_agg_lo[(size_t)NN * DD];
__device__ __nv_bfloat16 g_wt_hi[(size_t)3 * DD * DD];   // [WQ|WK|WV]^T  [1152(N), 384(K)]
__device__ __nv_bfloat16 g_wt_lo[(size_t)3 * DD * DD];
__device__ __nv_bfloat16 g_wo_hi[(size_t)DD * DD];       // WO^T [384, 384]
__device__ __nv_bfloat16 g_wo_lo[(size_t)DD * DD];

// ---------------- PTX helpers (baseline features only; PTX target is compute_103) ----------------
__device__ __forceinline__ uint32_t smem_to_u32(const void* p) {
    uint32_t a;
    asm("{ .reg .u64 t; cvta.to.shared.u64 t, %1; cvt.u32.u64 %0, t; }" : "=r"(a) : "l"(p));
    return a;
}
__device__ __forceinline__ void ldsm_x4(uint32_t* r, uint32_t addr) {
    asm volatile("ldmatrix.sync.aligned.m8n8.x4.shared.b16 {%0,%1,%2,%3}, [%4];"
        : "=r"(r[0]), "=r"(r[1]), "=r"(r[2]), "=r"(r[3]) : "r"(addr));
}
__device__ __forceinline__ void mma_bf16(float* c, const uint32_t* a, const uint32_t* b) {
    asm volatile(
        "mma.sync.aligned.m16n8k16.row.col.f32.bf16.bf16.f32 "
        "{%0,%1,%2,%3}, {%4,%5,%6,%7}, {%8,%9}, {%0,%1,%2,%3};"
        : "+f"(c[0]), "+f"(c[1]), "+f"(c[2]), "+f"(c[3])
        : "r"(a[0]), "r"(a[1]), "r"(a[2]), "r"(a[3]), "r"(b[0]), "r"(b[1]));
}
__device__ __forceinline__ void cp16(uint32_t dst, const void* src, bool valid) {
    int sz = valid ? 16 : 0;
    asm volatile("cp.async.cg.shared.global [%0], [%1], 16, %2;"
        :: "r"(dst), "l"(src), "r"(sz) : "memory");
}

// smem geometry: 4 operand arrays (Ahi,Alo,Bhi,Blo), 128 rows x 80B pitch, double-buffered
#define PITCH 80
#define ARR   10240          // 128 * 80
#define STG   40960          // 4 * ARR
#define SM_TOTAL (2 * STG)   // 81920

// ---------------- bf16x3 HMMA GEMM ----------------
// C[m, colBase+n] = sum_k A[m,k] * Bt[bx*128+n, k]  (+resid)
__global__ __launch_bounds__(256)
void gemm_tc(const __nv_bfloat16* __restrict__ Ahi, const __nv_bfloat16* __restrict__ Alo,
             const __nv_bfloat16* __restrict__ Bhi, const __nv_bfloat16* __restrict__ Blo,
             float* __restrict__ C0, float* __restrict__ C1, float* __restrict__ C2,
             int M, const float* __restrict__ resid)
{
    extern __shared__ char smem[];
    const uint32_t sb = smem_to_u32(smem);
    const int tid = threadIdx.x;
    const int wid = tid >> 5;
    const int lane = tid & 31;
    const int warp_m = wid & 1;
    const int warp_n = wid >> 1;
    const int rowBase = blockIdx.y * 128;
    const int mat = blockIdx.x / 3;
    const int colBase = (blockIdx.x % 3) * 128;
    const int btRowBase = blockIdx.x * 128;
    float* C = (mat == 0) ? C0 : (mat == 1 ? C1 : C2);

    float acc[4][4][4];
#pragma unroll
    for (int i = 0; i < 4; i++)
#pragma unroll
        for (int j = 0; j < 4; j++)
#pragma unroll
            for (int l = 0; l < 4; l++) acc[i][j][l] = 0.0f;

    const __nv_bfloat16* srcA[2] = { Ahi, Alo };
    const __nv_bfloat16* srcB[2] = { Bhi, Blo };

    auto load_stage = [&](int buf, int s) {
        const int k0 = s * 32;
#pragma unroll
        for (int i = 0; i < 8; i++) {
            int id = i * 256 + tid;
            int arr = id >> 9;
            int cid = id & 511;
            int row = cid >> 2;
            int c = cid & 3;
            uint32_t dst = sb + buf * STG + arr * ARR + row * PITCH + c * 16;
            const __nv_bfloat16* src;
            bool valid = true;
            if (arr < 2) {
                int gRow = rowBase + row;
                valid = (gRow < M);
                int gr = valid ? gRow : 0;
                src = srcA[arr] + (size_t)gr * DD + k0 + c * 8;
            } else {
                src = srcB[arr - 2] + (size_t)(btRowBase + row) * DD + k0 + c * 8;
            }
            cp16(dst, src, valid);
        }
        asm volatile("cp.async.commit_group;" ::: "memory");
    };

    load_stage(0, 0);

    for (int s = 0; s < 12; s++) {
        if (s + 1 < 12) {
            load_stage((s + 1) & 1, s + 1);
            asm volatile("cp.async.wait_group 1;" ::: "memory");
        } else {
            asm volatile("cp.async.wait_group 0;" ::: "memory");
        }
        __syncthreads();

        const uint32_t st = sb + (s & 1) * STG;
#pragma unroll
        for (int kk = 0; kk < 2; kk++) {
            uint32_t ah[4][4], al[4][4], bh[2][4], bl[2][4];
            const int arow = warp_m * 64;
#pragma unroll
            for (int mt = 0; mt < 4; mt++) {
                uint32_t addr = st + (uint32_t)((arow + mt * 16 + (lane & 15)) * PITCH
                              + kk * 32 + ((lane >> 4) & 1) * 16);
                ldsm_x4(ah[mt], addr);
                ldsm_x4(al[mt], addr + ARR);
            }
#pragma unroll
            for (int p = 0; p < 2; p++) {
                int grp = lane >> 3;
                int row = warp_n * 32 + (p * 2 + (grp >> 1)) * 8 + (lane & 7);
                uint32_t addr = st + 2 * ARR + (uint32_t)(row * PITCH
                              + kk * 32 + (grp & 1) * 16);
                ldsm_x4(bh[p], addr);
                ldsm_x4(bl[p], addr + ARR);
            }
#pragma unroll
            for (int mt = 0; mt < 4; mt++) {
#pragma unroll
                for (int nt = 0; nt < 4; nt++) {
                    const uint32_t* B2h = &bh[nt >> 1][(nt & 1) * 2];
                    const uint32_t* B2l = &bl[nt >> 1][(nt & 1) * 2];
                    mma_bf16(acc[mt][nt], ah[mt], B2h);
                    mma_bf16(acc[mt][nt], ah[mt], B2l);
                    mma_bf16(acc[mt][nt], al[mt], B2h);
                }
            }
        }
        __syncthreads();
    }

#pragma unroll
    for (int mt = 0; mt < 4; mt++) {
        int r0 = rowBase + warp_m * 64 + mt * 16 + (lane >> 2);
#pragma unroll
        for (int nt = 0; nt < 4; nt++) {
            int col = colBase + warp_n * 32 + nt * 8 + (lane & 3) * 2;
#pragma unroll
            for (int half = 0; half < 2; half++) {
                int r = r0 + half * 8;
                if (r >= M) continue;
                size_t off = (size_t)r * DD + col;
                float2 v = make_float2(acc[mt][nt][half * 2], acc[mt][nt][half * 2 + 1]);
                if (resid) {
                    float2 rv = *reinterpret_cast<const float2*>(resid + off);
                    v.x += rv.x; v.y += rv.y;
                }
                *reinterpret_cast<float2*>(C + off) = v;
            }
        }
    }
}

// ---------------- conversions ----------------
__global__ __launch_bounds__(256) void conv_emb(const float* __restrict__ emb) {
    int idx = blockIdx.x * 256 + threadIdx.x;
    if (idx >= NN * DD) return;
    float x = emb[idx];
    __nv_bfloat16 hi = __float2bfloat16(x);
    __nv_bfloat16 lo = __float2bfloat16(x - __bfloat162float(hi));
    g_emb_hi[idx] = hi;
    g_emb_lo[idx] = lo;
}

// weights transpose/split; also zeroes the degree histogram (idx < NN)
__global__ __launch_bounds__(256) void conv_weights(
    const float* __restrict__ WQ, const float* __restrict__ WK,
    const float* __restrict__ WV, const float* __restrict__ WO)
{
    int idx = blockIdx.x * 256 + threadIdx.x;
    if (idx < NN) g_deg[idx] = 0;
    if (idx >= 4 * DD * DD) return;
    int mat = idx / (DD * DD);
    int rem = idx - mat * (DD * DD);
    int n = rem / DD;
    int k = rem - n * DD;
    const float* W = (mat == 0) ? WQ : (mat == 1 ? WK : (mat == 2 ? WV : WO));
    float x = W[(size_t)k * DD + n];
    __nv_bfloat16 hi = __float2bfloat16(x);
    __nv_bfloat16 lo = __float2bfloat16(x - __bfloat162float(hi));
    if (mat < 3) {
        size_t o = (size_t)mat * DD * DD + (size_t)n * DD + k;
        g_wt_hi[o] = hi; g_wt_lo[o] = lo;
    } else {
        size_t o = (size_t)n * DD + k;
        g_wo_hi[o] = hi; g_wo_lo[o] = lo;
    }
}

// ---------------- CSR build ----------------
__global__ __launch_bounds__(256) void hist_kernel(const int* __restrict__ dst) {
    int e = blockIdx.x * 256 + threadIdx.x;
    if (e < EE) atomicAdd(&g_deg[dst[e]], 1);
}

__device__ __forceinline__ int warp_incl_scan(int x, int lane) {
#pragma unroll
    for (int off = 1; off < 32; off <<= 1) {
        int v = __shfl_up_sync(0xffffffffu, x, off);
        if (lane >= off) x += v;
    }
    return x;
}

// single-block exclusive scan over g_deg -> g_rowptr / g_cursor
__global__ __launch_bounds__(1024) void scan_kernel() {
    __shared__ int swarp[32];
    __shared__ int carry_s;
    const int tid = threadIdx.x;
    const int w = tid >> 5, lane = tid & 31;
    if (tid == 0) carry_s = 0;
    __syncthreads();
    for (int base = 0; base < NN; base += 1024) {
        int idx = base + tid;
        int x = (idx < NN) ? g_deg[idx] : 0;
        int incl = warp_incl_scan(x, lane);
        if (lane == 31) swarp[w] = incl;
        __syncthreads();
        if (w == 0) {
            int t = swarp[lane];
            t = warp_incl_scan(t, lane);
            swarp[lane] = t;
        }
        __syncthreads();
        int woff = (w > 0) ? swarp[w - 1] : 0;
        incl += woff;
        int carry = carry_s;
        __syncthreads();
        if (idx < NN) {
            int ex = carry + incl - x;
            g_rowptr[idx] = ex;
            g_cursor[idx] = ex;
        }
        if (tid == 1023) carry_s = carry + incl;
        __syncthreads();
    }
    if (threadIdx.x == 0) g_rowptr[NN] = carry_s;
}

__global__ __launch_bounds__(256) void scatter_kernel(
    const int* __restrict__ src, const int* __restrict__ dst,
    const float* __restrict__ eattr)
{
    int e = blockIdx.x * 256 + threadIdx.x;
    if (e >= EE) return;
    int t = dst[e];
    int pos = atomicAdd(&g_cursor[t], 1);
    g_esrc[pos] = src[e];
    g_eea[pos] = eattr[e];
}

// ---------------- fused node-parallel attention aggregate ----------------
// warp per node: online softmax over incoming edges, register accumulator,
// writes normalized agg directly as bf16 hi/lo.
__global__ __launch_bounds__(256) void node_fused(const float* __restrict__ WE) {
    const int n = blockIdx.x * 8 + (threadIdx.x >> 5);
    if (n >= NN) return;
    const int lane = threadIdx.x & 31;

    float qv[12], we[12];
    const float* qrow = g_q + (size_t)n * DD;
#pragma unroll
    for (int j = 0; j < 6; j++) {
        int d0 = lane + 32 * j;
        qv[j]     = qrow[d0];
        qv[j + 6] = qrow[d0 + DHH];
        we[j]     = WE[d0];
        we[j + 6] = WE[d0 + DHH];
    }

    // qe_h = q . WE_h
    float qe0 = 0.f, qe1 = 0.f;
#pragma unroll
    for (int j = 0; j < 6; j++) { qe0 += qv[j] * we[j]; qe1 += qv[j + 6] * we[j + 6]; }
#pragma unroll
    for (int o = 16; o > 0; o >>= 1) {
        qe0 += __shfl_xor_sync(0xffffffffu, qe0, o);
        qe1 += __shfl_xor_sync(0xffffffffu, qe1, o);
    }

    const int beg = g_rowptr[n];
    const int end = g_rowptr[n + 1];

    float m0 = -3.0e38f, m1 = -3.0e38f;
    float den0 = 0.f, den1 = 0.f, sexa0 = 0.f, sexa1 = 0.f;
    float acc[12];
#pragma unroll
    for (int j = 0; j < 12; j++) acc[j] = 0.f;

    const float SCL = 0.07216878364870323f;  // 1/sqrt(192)

    for (int i = beg; i < end; i++) {
        const int s = g_esrc[i];
        const float ea = g_eea[i];
        const float* krow = g_k + (size_t)s * DD;
        const float* vrow = g_v + (size_t)s * DD;

        float kv[12], vv[12];
#pragma unroll
        for (int j = 0; j < 6; j++) {
            int d0 = lane + 32 * j;
            kv[j]     = krow[d0];
            kv[j + 6] = krow[d0 + DHH];
            vv[j]     = vrow[d0];
            vv[j + 6] = vrow[d0 + DHH];
        }
        float d0s = 0.f, d1s = 0.f;
#pragma unroll
        for (int j = 0; j < 6; j++) { d0s += qv[j] * kv[j]; d1s += qv[j + 6] * kv[j + 6]; }
#pragma unroll
        for (int o = 16; o > 0; o >>= 1) {
            d0s += __shfl_xor_sync(0xffffffffu, d0s, o);
            d1s += __shfl_xor_sync(0xffffffffu, d1s, o);
        }
        float s0 = (d0s + ea * qe0) * SCL;
        float s1 = (d1s + ea * qe1) * SCL;

        float nm0 = fmaxf(m0, s0), nm1 = fmaxf(m1, s1);
        float sc0 = expf(m0 - nm0), sc1 = expf(m1 - nm1);
        float ex0 = expf(s0 - nm0), ex1 = expf(s1 - nm1);
        den0 = den0 * sc0 + ex0;  den1 = den1 * sc1 + ex1;
        sexa0 = sexa0 * sc0 + ex0 * ea;  sexa1 = sexa1 * sc1 + ex1 * ea;
#pragma unroll
        for (int j = 0; j < 6; j++) {
            acc[j]     = acc[j]     * sc0 + ex0 * vv[j];
            acc[j + 6] = acc[j + 6] * sc1 + ex1 * vv[j + 6];
        }
        m0 = nm0; m1 = nm1;
    }

    const float inv0 = 1.0f / (den0 + 1e-16f);
    const float inv1 = 1.0f / (den1 + 1e-16f);
    size_t base = (size_t)n * DD;
#pragma unroll
    for (int j = 0; j < 6; j++) {
        int d0 = lane + 32 * j;
        float o0 = (acc[j]     + sexa0 * we[j])     * inv0;
        float o1 = (acc[j + 6] + sexa1 * we[j + 6]) * inv1;
        __nv_bfloat16 h0 = __float2bfloat16(o0);
        __nv_bfloat16 h1 = __float2bfloat16(o1);
        g_agg_hi[base + d0]       = h0;
        g_agg_lo[base + d0]       = __float2bfloat16(o0 - __bfloat162float(h0));
        g_agg_hi[base + d0 + DHH] = h1;
        g_agg_lo[base + d0 + DHH] = __float2bfloat16(o1 - __bfloat162float(h1));
    }
}

// ---------------- layernorm ----------------
__global__ __launch_bounds__(128) void ln_kernel(
    const float* __restrict__ gw, const float* __restrict__ bw,
    float* __restrict__ out)
{
    const int n = blockIdx.x;
    const int tid = threadIdx.x;
    const float* x = g_tmp + (size_t)n * DD;
    float v0 = x[tid], v1 = x[tid + 128], v2 = x[tid + 256];
    float s = v0 + v1 + v2;
    float sq = v0 * v0 + v1 * v1 + v2 * v2;
#pragma unroll
    for (int o = 16; o > 0; o >>= 1) {
        s  += __shfl_down_sync(0xffffffffu, s, o);
        sq += __shfl_down_sync(0xffffffffu, sq, o);
    }
    __shared__ float ss[4], ssq[4];
    int w = tid >> 5, l = tid & 31;
    if (l == 0) { ss[w] = s; ssq[w] = sq; }
    __syncthreads();
    if (tid == 0) {
        float S = ss[0] + ss[1] + ss[2] + ss[3];
        float SQ = ssq[0] + ssq[1] + ssq[2] + ssq[3];
        float mu = S * (1.0f / DD);
        float var = SQ * (1.0f / DD) - mu * mu;
        ss[0] = mu;
        ssq[0] = rsqrtf(var + 1e-5f);
    }
    __syncthreads();
    float mu = ss[0], inv = ssq[0];
    size_t base = (size_t)n * DD;
    out[base + tid]       = (v0 - mu) * inv * gw[tid]       + bw[tid];
    out[base + tid + 128] = (v1 - mu) * inv * gw[tid + 128] + bw[tid + 128];
    out[base + tid + 256] = (v2 - mu) * inv * gw[tid + 256] + bw[tid + 256];
}

// ---------------- launch ----------------
extern "C" void kernel_launch(void* const* d_in, const int* in_sizes, int n_in,
                              void* d_out, int out_size)
{
    const float* emb   = (const float*)d_in[0];
    const int*   eidx  = (const int*)  d_in[1];
    const float* eattr = (const float*)d_in[2];
    const float* WQ    = (const float*)d_in[3];
    const float* WK    = (const float*)d_in[4];
    const float* WV    = (const float*)d_in[5];
    const float* WE    = (const float*)d_in[6];
    const float* WO    = (const float*)d_in[7];
    const float* ln_g  = (const float*)d_in[8];
    const float* ln_b  = (const float*)d_in[9];
    float* out = (float*)d_out;

    const int* src = eidx;
    const int* dst = eidx + EE;

    cudaFuncSetAttribute(gemm_tc, cudaFuncAttributeMaxDynamicSharedMemorySize, SM_TOTAL);

    float *dq, *dk, *dv, *dtmp;
    __nv_bfloat16 *dembh, *dembl, *daggh, *daggl, *dwth, *dwtl, *dwoh, *dwol;
    cudaGetSymbolAddress((void**)&dq,    g_q);
    cudaGetSymbolAddress((void**)&dk,    g_k);
    cudaGetSymbolAddress((void**)&dv,    g_v);
    cudaGetSymbolAddress((void**)&dtmp,  g_tmp);
    cudaGetSymbolAddress((void**)&dembh, g_emb_hi);
    cudaGetSymbolAddress((void**)&dembl, g_emb_lo);
    cudaGetSymbolAddress((void**)&daggh, g_agg_hi);
    cudaGetSymbolAddress((void**)&daggl, g_agg_lo);
    cudaGetSymbolAddress((void**)&dwth,  g_wt_hi);
    cudaGetSymbolAddress((void**)&dwtl,  g_wt_lo);
    cudaGetSymbolAddress((void**)&dwoh,  g_wo_hi);
    cudaGetSymbolAddress((void**)&dwol,  g_wo_lo);

    // conversions + CSR build
    conv_emb<<<(NN * DD + 255) / 256, 256>>>(emb);
    conv_weights<<<(4 * DD * DD + 255) / 256, 256>>>(WQ, WK, WV, WO);
    hist_kernel<<<(EE + 255) / 256, 256>>>(dst);
    scan_kernel<<<1, 1024>>>();
    scatter_kernel<<<(EE + 255) / 256, 256>>>(src, dst, eattr);

    const int MT = (NN + 127) / 128;
    // fused Q/K/V projections
    gemm_tc<<<dim3(9, MT), 256, SM_TOTAL>>>(dembh, dembl, dwth, dwtl,
                                            dq, dk, dv, NN, nullptr);

    // fused edge-conditioned attention + softmax + aggregation
    node_fused<<<(NN + 7) / 8, 256>>>(WE);

    // output projection + residual
    gemm_tc<<<dim3(3, MT), 256, SM_TOTAL>>>(daggh, daggl, dwoh, dwol,
                                            dtmp, dtmp, dtmp, NN, emb);

    ln_kernel<<<NN, 128>>>(ln_g, ln_b, out);
}

// round 5
// speedup vs baseline: 2.5544x; 1.1403x over previous
#include <cuda_runtime.h>
#include <cuda_bf16.h>
#include <math.h>
#include <stdint.h>

// Problem constants (fixed by the reference)
#define NN 50000
#define EE 200000
#define DD 384
#define HH 2
#define DHH 192

#define SCAN_BLK 1024
#define NSCAN ((NN + SCAN_BLK - 1) / SCAN_BLK)   // 49

// ---------------- device scratch (allocation-free requirement) ----------------
__device__ float g_q[(size_t)NN * DD];
__device__ float g_k[(size_t)NN * DD];
__device__ float g_v[(size_t)NN * DD];
__device__ float g_tmp[(size_t)NN * DD];

__device__ int   g_deg[NN];
__device__ int   g_rowptr[NN + 1];
__device__ int   g_cursor[NN];
__device__ int   g_blocksum[NSCAN];
__device__ int   g_esrc[EE];
__device__ float g_eea[EE];

__device__ __nv_bfloat16 g_emb_hi[(size_t)NN * DD];
__device__ __nv_bfloat16 g_emb_lo[(size_t)NN * DD];
__device__ __nv_bfloat16 g_agg_hi[(size_t)NN * DD];
__device__ __nv_bfloat16 g_agg_lo[(size_t)NN * DD];
__device__ __nv_bfloat16 g_wt_hi[(size_t)3 * DD * DD];   // [WQ|WK|WV]^T  [1152(N), 384(K)]
__device__ __nv_bfloat16 g_wt_lo[(size_t)3 * DD * DD];
__device__ __nv_bfloat16 g_wo_hi[(size_t)DD * DD];       // WO^T [384, 384]
__device__ __nv_bfloat16 g_wo_lo[(size_t)DD * DD];

// ---------------- PTX helpers (baseline features only; PTX target is compute_103) ----------------
__device__ __forceinline__ uint32_t smem_to_u32(const void* p) {
    uint32_t a;
    asm("{ .reg .u64 t; cvta.to.shared.u64 t, %1; cvt.u32.u64 %0, t; }" : "=r"(a) : "l"(p));
    return a;
}
__device__ __forceinline__ void ldsm_x4(uint32_t* r, uint32_t addr) {
    asm volatile("ldmatrix.sync.aligned.m8n8.x4.shared.b16 {%0,%1,%2,%3}, [%4];"
        : "=r"(r[0]), "=r"(r[1]), "=r"(r[2]), "=r"(r[3]) : "r"(addr));
}
__device__ __forceinline__ void mma_bf16(float* c, const uint32_t* a, const uint32_t* b) {
    asm volatile(
        "mma.sync.aligned.m16n8k16.row.col.f32.bf16.bf16.f32 "
        "{%0,%1,%2,%3}, {%4,%5,%6,%7}, {%8,%9}, {%0,%1,%2,%3};"
        : "+f"(c[0]), "+f"(c[1]), "+f"(c[2]), "+f"(c[3])
        : "r"(a[0]), "r"(a[1]), "r"(a[2]), "r"(a[3]), "r"(b[0]), "r"(b[1]));
}
__device__ __forceinline__ void cp16(uint32_t dst, const void* src, bool valid) {
    int sz = valid ? 16 : 0;
    asm volatile("cp.async.cg.shared.global [%0], [%1], 16, %2;"
        :: "r"(dst), "l"(src), "r"(sz) : "memory");
}

// smem geometry: 4 operand arrays (Ahi,Alo,Bhi,Blo), 128 rows x 80B pitch, double-buffered
#define PITCH 80
#define ARR   10240          // 128 * 80
#define STG   40960          // 4 * ARR
#define SM_TOTAL (2 * STG)   // 81920

// ---------------- bf16x3 HMMA GEMM ----------------
// C[m, colBase+n] = sum_k A[m,k] * Bt[bx*128+n, k]  (+resid)
__global__ __launch_bounds__(256)
void gemm_tc(const __nv_bfloat16* __restrict__ Ahi, const __nv_bfloat16* __restrict__ Alo,
             const __nv_bfloat16* __restrict__ Bhi, const __nv_bfloat16* __restrict__ Blo,
             float* __restrict__ C0, float* __restrict__ C1, float* __restrict__ C2,
             int M, const float* __restrict__ resid)
{
    extern __shared__ char smem[];
    const uint32_t sb = smem_to_u32(smem);
    const int tid = threadIdx.x;
    const int wid = tid >> 5;
    const int lane = tid & 31;
    const int warp_m = wid & 1;
    const int warp_n = wid >> 1;
    const int rowBase = blockIdx.y * 128;
    const int mat = blockIdx.x / 3;
    const int colBase = (blockIdx.x % 3) * 128;
    const int btRowBase = blockIdx.x * 128;
    float* C = (mat == 0) ? C0 : (mat == 1 ? C1 : C2);

    float acc[4][4][4];
#pragma unroll
    for (int i = 0; i < 4; i++)
#pragma unroll
        for (int j = 0; j < 4; j++)
#pragma unroll
            for (int l = 0; l < 4; l++) acc[i][j][l] = 0.0f;

    const __nv_bfloat16* srcA[2] = { Ahi, Alo };
    const __nv_bfloat16* srcB[2] = { Bhi, Blo };

    auto load_stage = [&](int buf, int s) {
        const int k0 = s * 32;
#pragma unroll
        for (int i = 0; i < 8; i++) {
            int id = i * 256 + tid;
            int arr = id >> 9;
            int cid = id & 511;
            int row = cid >> 2;
            int c = cid & 3;
            uint32_t dst = sb + buf * STG + arr * ARR + row * PITCH + c * 16;
            const __nv_bfloat16* src;
            bool valid = true;
            if (arr < 2) {
                int gRow = rowBase + row;
                valid = (gRow < M);
                int gr = valid ? gRow : 0;
                src = srcA[arr] + (size_t)gr * DD + k0 + c * 8;
            } else {
                src = srcB[arr - 2] + (size_t)(btRowBase + row) * DD + k0 + c * 8;
            }
            cp16(dst, src, valid);
        }
        asm volatile("cp.async.commit_group;" ::: "memory");
    };

    load_stage(0, 0);

    for (int s = 0; s < 12; s++) {
        asm volatile("cp.async.wait_group 0;" ::: "memory");
        __syncthreads();                         // single barrier per stage
        if (s + 1 < 12) load_stage((s + 1) & 1, s + 1);   // overlaps compute(s)

        const uint32_t st = sb + (s & 1) * STG;
#pragma unroll
        for (int kk = 0; kk < 2; kk++) {
            uint32_t ah[4][4], al[4][4], bh[2][4], bl[2][4];
            const int arow = warp_m * 64;
#pragma unroll
            for (int mt = 0; mt < 4; mt++) {
                uint32_t addr = st + (uint32_t)((arow + mt * 16 + (lane & 15)) * PITCH
                              + kk * 32 + ((lane >> 4) & 1) * 16);
                ldsm_x4(ah[mt], addr);
                ldsm_x4(al[mt], addr + ARR);
            }
#pragma unroll
            for (int p = 0; p < 2; p++) {
                int grp = lane >> 3;
                int row = warp_n * 32 + (p * 2 + (grp >> 1)) * 8 + (lane & 7);
                uint32_t addr = st + 2 * ARR + (uint32_t)(row * PITCH
                              + kk * 32 + (grp & 1) * 16);
                ldsm_x4(bh[p], addr);
                ldsm_x4(bl[p], addr + ARR);
            }
#pragma unroll
            for (int mt = 0; mt < 4; mt++) {
#pragma unroll
                for (int nt = 0; nt < 4; nt++) {
                    const uint32_t* B2h = &bh[nt >> 1][(nt & 1) * 2];
                    const uint32_t* B2l = &bl[nt >> 1][(nt & 1) * 2];
                    mma_bf16(acc[mt][nt], ah[mt], B2h);
                    mma_bf16(acc[mt][nt], ah[mt], B2l);
                    mma_bf16(acc[mt][nt], al[mt], B2h);
                }
            }
        }
    }

#pragma unroll
    for (int mt = 0; mt < 4; mt++) {
        int r0 = rowBase + warp_m * 64 + mt * 16 + (lane >> 2);
#pragma unroll
        for (int nt = 0; nt < 4; nt++) {
            int col = colBase + warp_n * 32 + nt * 8 + (lane & 3) * 2;
#pragma unroll
            for (int half = 0; half < 2; half++) {
                int r = r0 + half * 8;
                if (r >= M) continue;
                size_t off = (size_t)r * DD + col;
                float2 v = make_float2(acc[mt][nt][half * 2], acc[mt][nt][half * 2 + 1]);
                if (resid) {
                    float2 rv = *reinterpret_cast<const float2*>(resid + off);
                    v.x += rv.x; v.y += rv.y;
                }
                *reinterpret_cast<float2*>(C + off) = v;
            }
        }
    }
}

// ---------------- conversions ----------------
__global__ __launch_bounds__(256) void conv_emb(const float* __restrict__ emb) {
    int idx = blockIdx.x * 256 + threadIdx.x;
    if (idx >= NN * DD) return;
    float x = emb[idx];
    __nv_bfloat16 hi = __float2bfloat16(x);
    __nv_bfloat16 lo = __float2bfloat16(x - __bfloat162float(hi));
    g_emb_hi[idx] = hi;
    g_emb_lo[idx] = lo;
}

__global__ __launch_bounds__(256) void conv_weights(
    const float* __restrict__ WQ, const float* __restrict__ WK,
    const float* __restrict__ WV, const float* __restrict__ WO)
{
    int idx = blockIdx.x * 256 + threadIdx.x;
    if (idx >= 4 * DD * DD) return;
    int mat = idx / (DD * DD);
    int rem = idx - mat * (DD * DD);
    int n = rem / DD;
    int k = rem - n * DD;
    const float* W = (mat == 0) ? WQ : (mat == 1 ? WK : (mat == 2 ? WV : WO));
    float x = W[(size_t)k * DD + n];
    __nv_bfloat16 hi = __float2bfloat16(x);
    __nv_bfloat16 lo = __float2bfloat16(x - __bfloat162float(hi));
    if (mat < 3) {
        size_t o = (size_t)mat * DD * DD + (size_t)n * DD + k;
        g_wt_hi[o] = hi; g_wt_lo[o] = lo;
    } else {
        size_t o = (size_t)n * DD + k;
        g_wo_hi[o] = hi; g_wo_lo[o] = lo;
    }
}

// ---------------- CSR build (side stream) ----------------
__global__ __launch_bounds__(256) void zero_deg() {
    int i = blockIdx.x * 256 + threadIdx.x;
    if (i < NN) g_deg[i] = 0;
}

__global__ __launch_bounds__(256) void hist_kernel(const int* __restrict__ dst) {
    int e = blockIdx.x * 256 + threadIdx.x;
    if (e < EE) atomicAdd(&g_deg[dst[e]], 1);
}

__device__ __forceinline__ int warp_incl_scan(int x, int lane) {
#pragma unroll
    for (int off = 1; off < 32; off <<= 1) {
        int v = __shfl_up_sync(0xffffffffu, x, off);
        if (lane >= off) x += v;
    }
    return x;
}

// phase A: per-block inclusive scan -> g_rowptr (temp), block totals
__global__ __launch_bounds__(1024) void scanA() {
    __shared__ int swarp[32];
    const int tid = threadIdx.x;
    const int w = tid >> 5, lane = tid & 31;
    int idx = blockIdx.x * 1024 + tid;
    int x = (idx < NN) ? g_deg[idx] : 0;
    int incl = warp_incl_scan(x, lane);
    if (lane == 31) swarp[w] = incl;
    __syncthreads();
    if (w == 0) {
        int t = swarp[lane];
        t = warp_incl_scan(t, lane);
        swarp[lane] = t;
    }
    __syncthreads();
    int woff = (w > 0) ? swarp[w - 1] : 0;
    incl += woff;
    if (idx < NN) g_rowptr[idx] = incl;
    if (tid == 1023) g_blocksum[blockIdx.x] = incl;
}

// phase B: scan 49 block totals (single block of 64)
__global__ __launch_bounds__(64) void scanB() {
    __shared__ int sh[64];
    const int tid = threadIdx.x;
    int v = (tid < NSCAN) ? g_blocksum[tid] : 0;
    sh[tid] = v;
    for (int off = 1; off < 64; off <<= 1) {
        __syncthreads();
        int t = (tid >= off) ? sh[tid - off] : 0;
        __syncthreads();
        sh[tid] += t;
    }
    __syncthreads();
    if (tid < NSCAN) g_blocksum[tid] = sh[tid] - v;  // exclusive
    if (tid == 63) g_rowptr[NN] = sh[63];
}

// phase C: apply offsets, produce exclusive rowptr + cursor
__global__ __launch_bounds__(1024) void scanC() {
    int idx = blockIdx.x * 1024 + threadIdx.x;
    if (idx >= NN) return;
    int ex = g_blocksum[blockIdx.x] + g_rowptr[idx] - g_deg[idx];
    g_rowptr[idx] = ex;
    g_cursor[idx] = ex;
}

__global__ __launch_bounds__(256) void scatter_kernel(
    const int* __restrict__ src, const int* __restrict__ dst,
    const float* __restrict__ eattr)
{
    int e = blockIdx.x * 256 + threadIdx.x;
    if (e >= EE) return;
    int t = dst[e];
    int pos = atomicAdd(&g_cursor[t], 1);
    g_esrc[pos] = src[e];
    g_eea[pos] = eattr[e];
}

// ---------------- fused attention aggregate: warp per (node, head) ----------------
__global__ __launch_bounds__(256) void node_fused(const float* __restrict__ WE) {
    const int gw = blockIdx.x * 8 + (threadIdx.x >> 5);
    const int n = gw >> 1;
    if (n >= NN) return;
    const int h = gw & 1;
    const int hb = h * DHH;
    const int lane = threadIdx.x & 31;

    float qv[6], we[6];
    const float* qrow = g_q + (size_t)n * DD + hb;
    const float* werow = WE + hb;
#pragma unroll
    for (int j = 0; j < 6; j++) {
        int d = lane + 32 * j;
        qv[j] = qrow[d];
        we[j] = werow[d];
    }

    // qe = q_h . WE_h
    float qe = 0.f;
#pragma unroll
    for (int j = 0; j < 6; j++) qe += qv[j] * we[j];
#pragma unroll
    for (int o = 16; o > 0; o >>= 1) qe += __shfl_xor_sync(0xffffffffu, qe, o);

    const int beg = g_rowptr[n];
    const int end = g_rowptr[n + 1];

    float m0 = -3.0e38f, den = 0.f, sexa = 0.f;
    float acc[6];
#pragma unroll
    for (int j = 0; j < 6; j++) acc[j] = 0.f;

    const float SCL = 0.07216878364870323f;  // 1/sqrt(192)

    for (int i = beg; i < end; i++) {
        const int s = g_esrc[i];
        const float ea = g_eea[i];
        const float* krow = g_k + (size_t)s * DD + hb;
        const float* vrow = g_v + (size_t)s * DD + hb;

        float kv[6], vv[6];
#pragma unroll
        for (int j = 0; j < 6; j++) {
            int d = lane + 32 * j;
            kv[j] = krow[d];
            vv[j] = vrow[d];
        }
        float ds = 0.f;
#pragma unroll
        for (int j = 0; j < 6; j++) ds += qv[j] * kv[j];
#pragma unroll
        for (int o = 16; o > 0; o >>= 1) ds += __shfl_xor_sync(0xffffffffu, ds, o);
        float s0 = (ds + ea * qe) * SCL;

        float nm = fmaxf(m0, s0);
        float sc = expf(m0 - nm);
        float ex = expf(s0 - nm);
        den = den * sc + ex;
        sexa = sexa * sc + ex * ea;
#pragma unroll
        for (int j = 0; j < 6; j++) acc[j] = acc[j] * sc + ex * vv[j];
        m0 = nm;
    }

    const float inv = 1.0f / (den + 1e-16f);
    size_t base = (size_t)n * DD + hb;
#pragma unroll
    for (int j = 0; j < 6; j++) {
        int d = lane + 32 * j;
        float o0 = (acc[j] + sexa * we[j]) * inv;
        __nv_bfloat16 hi = __float2bfloat16(o0);
        g_agg_hi[base + d] = hi;
        g_agg_lo[base + d] = __float2bfloat16(o0 - __bfloat162float(hi));
    }
}

// ---------------- layernorm ----------------
__global__ __launch_bounds__(128) void ln_kernel(
    const float* __restrict__ gw, const float* __restrict__ bw,
    float* __restrict__ out)
{
    const int n = blockIdx.x;
    const int tid = threadIdx.x;
    const float* x = g_tmp + (size_t)n * DD;
    float v0 = x[tid], v1 = x[tid + 128], v2 = x[tid + 256];
    float s = v0 + v1 + v2;
    float sq = v0 * v0 + v1 * v1 + v2 * v2;
#pragma unroll
    for (int o = 16; o > 0; o >>= 1) {
        s  += __shfl_down_sync(0xffffffffu, s, o);
        sq += __shfl_down_sync(0xffffffffu, sq, o);
    }
    __shared__ float ss[4], ssq[4];
    int w = tid >> 5, l = tid & 31;
    if (l == 0) { ss[w] = s; ssq[w] = sq; }
    __syncthreads();
    if (tid == 0) {
        float S = ss[0] + ss[1] + ss[2] + ss[3];
        float SQ = ssq[0] + ssq[1] + ssq[2] + ssq[3];
        float mu = S * (1.0f / DD);
        float var = SQ * (1.0f / DD) - mu * mu;
        ss[0] = mu;
        ssq[0] = rsqrtf(var + 1e-5f);
    }
    __syncthreads();
    float mu = ss[0], inv = ssq[0];
    size_t base = (size_t)n * DD;
    out[base + tid]       = (v0 - mu) * inv * gw[tid]       + bw[tid];
    out[base + tid + 128] = (v1 - mu) * inv * gw[tid + 128] + bw[tid + 128];
    out[base + tid + 256] = (v2 - mu) * inv * gw[tid + 256] + bw[tid + 256];
}

// ---------------- launch ----------------
extern "C" void kernel_launch(void* const* d_in, const int* in_sizes, int n_in,
                              void* d_out, int out_size)
{
    const float* emb   = (const float*)d_in[0];
    const int*   eidx  = (const int*)  d_in[1];
    const float* eattr = (const float*)d_in[2];
    const float* WQ    = (const float*)d_in[3];
    const float* WK    = (const float*)d_in[4];
    const float* WV    = (const float*)d_in[5];
    const float* WE    = (const float*)d_in[6];
    const float* WO    = (const float*)d_in[7];
    const float* ln_g  = (const float*)d_in[8];
    const float* ln_b  = (const float*)d_in[9];
    float* out = (float*)d_out;

    const int* src = eidx;
    const int* dst = eidx + EE;

    static bool inited = false;
    static cudaStream_t s_side;
    static cudaEvent_t ev_fork, ev_join;
    if (!inited) {
        cudaFuncSetAttribute(gemm_tc, cudaFuncAttributeMaxDynamicSharedMemorySize, SM_TOTAL);
        cudaStreamCreateWithFlags(&s_side, cudaStreamNonBlocking);
        cudaEventCreateWithFlags(&ev_fork, cudaEventDisableTiming);
        cudaEventCreateWithFlags(&ev_join, cudaEventDisableTiming);
        inited = true;
    }

    float *dq, *dk, *dv, *dtmp;
    __nv_bfloat16 *dembh, *dembl, *daggh, *daggl, *dwth, *dwtl, *dwoh, *dwol;
    cudaGetSymbolAddress((void**)&dq,    g_q);
    cudaGetSymbolAddress((void**)&dk,    g_k);
    cudaGetSymbolAddress((void**)&dv,    g_v);
    cudaGetSymbolAddress((void**)&dtmp,  g_tmp);
    cudaGetSymbolAddress((void**)&dembh, g_emb_hi);
    cudaGetSymbolAddress((void**)&dembl, g_emb_lo);
    cudaGetSymbolAddress((void**)&daggh, g_agg_hi);
    cudaGetSymbolAddress((void**)&daggl, g_agg_lo);
    cudaGetSymbolAddress((void**)&dwth,  g_wt_hi);
    cudaGetSymbolAddress((void**)&dwtl,  g_wt_lo);
    cudaGetSymbolAddress((void**)&dwoh,  g_wo_hi);
    cudaGetSymbolAddress((void**)&dwol,  g_wo_lo);

    // ---- fork: CSR build on side stream, overlapped with conv + QKV GEMM ----
    cudaEventRecord(ev_fork, 0);
    cudaStreamWaitEvent(s_side, ev_fork, 0);
    zero_deg<<<(NN + 255) / 256, 256, 0, s_side>>>();
    hist_kernel<<<(EE + 255) / 256, 256, 0, s_side>>>(dst);
    scanA<<<NSCAN, 1024, 0, s_side>>>();
    scanB<<<1, 64, 0, s_side>>>();
    scanC<<<NSCAN, 1024, 0, s_side>>>();
    scatter_kernel<<<(EE + 255) / 256, 256, 0, s_side>>>(src, dst, eattr);
    cudaEventRecord(ev_join, s_side);

    // ---- main stream: conversions + QKV projections ----
    conv_emb<<<(NN * DD + 255) / 256, 256>>>(emb);
    conv_weights<<<(4 * DD * DD + 255) / 256, 256>>>(WQ, WK, WV, WO);

    const int MT = (NN + 127) / 128;
    gemm_tc<<<dim3(9, MT), 256, SM_TOTAL>>>(dembh, dembl, dwth, dwtl,
                                            dq, dk, dv, NN, nullptr);

    // ---- join, then fused attention ----
    cudaStreamWaitEvent(0, ev_join, 0);
    node_fused<<<(2 * NN + 7) / 8, 256>>>(WE);

    // output projection + residual
    gemm_tc<<<dim3(3, MT), 256, SM_TOTAL>>>(daggh, daggl, dwoh, dwol,
                                            dtmp, dtmp, dtmp, NN, emb);

    ln_kernel<<<NN, 128>>>(ln_g, ln_b, out);
}